// round 11
// baseline (speedup 1.0000x reference)
#include <cuda_runtime.h>
#include <cuda_fp16.h>
#include <cstdint>

#define LENGTH   262144
#define NFFT     2048
#define HOP      512
#define BATCH    16
#define FRAMES   513
#define NCOLS    (BATCH * FRAMES)      // 8208
#define NPAD     8448                  // 66 * 128
#define KP2      576                   // 513 live + pad (9 chunks of 64)
#define KC       64
#define NCH      (KP2 / KC)            // 9
#define MROWS    512
#define MT2      128
#define NT2      128
#define A_BYTES  (MT2 * 128)
#define B_BYTES  (NT2 * 128)
#define STAGE_BYTES (A_BYTES + B_BYTES) // 32768
#define STAGES   3
#define SMEM_TOTAL (STAGES * STAGE_BYTES) // 98304

// phase order: 0=even-cos(Pe), 1=odd-cos(Po), 2=even-sin(Me), 3=odd-sin(Mo)
__device__ __align__(16) __half g_W[4 * MROWS * KP2];   // 2.4 MB
__device__ __align__(16) __half g_B[4 * NPAD * KP2];    // 38.9 MB
__device__ __align__(16) float  g_win[520];

__device__ __forceinline__ uint32_t smem_u32(const void* p) {
    uint32_t a;
    asm("{ .reg .u64 t; cvta.to.shared.u64 t, %1; cvt.u32.u64 %0, t; }" : "=r"(a) : "l"(p));
    return a;
}
__device__ __forceinline__ void cpa(uint32_t dst, uint64_t gsrc) {
    asm volatile("cp.async.cg.shared.global [%0], [%1], 16;" :: "r"(dst), "l"(gsrc) : "memory");
}
__device__ __forceinline__ void ldsm4(uint32_t* r, uint32_t a) {
    asm volatile("ldmatrix.sync.aligned.m8n8.x4.shared.b16 {%0,%1,%2,%3}, [%4];"
        : "=r"(r[0]), "=r"(r[1]), "=r"(r[2]), "=r"(r[3]) : "r"(a));
}
__device__ __forceinline__ void mma16(float* c, const uint32_t* a, const uint32_t* b) {
    asm volatile("mma.sync.aligned.m16n8k16.row.col.f32.f16.f16.f32 "
        "{%0,%1,%2,%3}, {%4,%5,%6,%7}, {%8,%9}, {%0,%1,%2,%3};"
        : "+f"(c[0]), "+f"(c[1]), "+f"(c[2]), "+f"(c[3])
        : "r"(a[0]), "r"(a[1]), "r"(a[2]), "r"(a[3]), "r"(b[0]), "r"(b[1]));
}

// ---- prep 1: basis matrices + window table ----
__global__ __launch_bounds__(256) void build_W()
{
    int idx = blockIdx.x * 256 + threadIdx.x;
    if (idx < 513)
        g_win[idx] = 0.5f - 0.5f * cospif((float)idx / 1024.0f);
    if (idx >= MROWS * KP2) return;
    int m = idx / KP2;
    int n = idx - m * KP2;
    float ce = 0.f, co = 0.f, se = 0.f, so = 0.f;
    if (n <= 512) {
        float ue = (float)(m * n) / 512.0f;
        float uo = (float)((2 * m + 1) * n) / 1024.0f;
        ce = cospif(ue); se = sinpif(ue);
        co = cospif(uo); so = sinpif(uo);
    }
    g_W[0 * MROWS * KP2 + idx] = __float2half_rn(ce);
    g_W[1 * MROWS * KP2 + idx] = __float2half_rn(co);
    g_W[2 * MROWS * KP2 + idx] = __float2half_rn(se);
    g_W[3 * MROWS * KP2 + idx] = __float2half_rn(so);
}

__device__ __forceinline__ float xrefl(const float* xb, int i) {
    if (i < 0) i = -i;
    else if (i >= LENGTH) i = 2 * LENGTH - 2 - i;
    return xb[i];
}

// ---- prep 2: vectorized fold. 288 threads = 4 cols x 72 threads, 8 j per thread ----
__global__ __launch_bounds__(288) void build_B4v(const float* __restrict__ x,
                                                 float* __restrict__ out)
{
    __shared__ float alt4[4];
    const int tid = threadIdx.x;
    const int c   = tid / 72;          // column within block: 0..3
    const int u   = tid - c * 72;      // 0..71
    const int col = blockIdx.x * 4 + c;
    const int j0  = u * 8;             // 0..568

    if (tid < 4) alt4[tid] = 0.f;
    __syncthreads();

    __half* pe = g_B + 0 * (size_t)NPAD * KP2 + (size_t)col * KP2;
    __half* po = g_B + 1 * (size_t)NPAD * KP2 + (size_t)col * KP2;
    __half* me = g_B + 2 * (size_t)NPAD * KP2 + (size_t)col * KP2;
    __half* mo = g_B + 3 * (size_t)NPAD * KP2 + (size_t)col * KP2;

    float alt = 0.f;

    if (col >= NCOLS || j0 > 512) {
        // dead region: zero stores
        uint4 z = make_uint4(0u, 0u, 0u, 0u);
        *(uint4*)(pe + j0) = z; *(uint4*)(po + j0) = z;
        *(uint4*)(me + j0) = z; *(uint4*)(mo + j0) = z;
    } else {
        const int b = col / FRAMES;
        const int t = col - b * FRAMES;
        const float* __restrict__ xb = x + (size_t)b * LENGTH;
        const int base = t * HOP - 1024;

        float xa[8], xd[8], xr2[8], xr1[8];   // xr2 = x[base+2048-j], xr1 = x[base+1024-j]
        if (t >= 2 && t <= 509) {
            // fast path: all indices in [0, LENGTH)
            float4 v0 = *(const float4*)(xb + base + j0);
            float4 v1 = *(const float4*)(xb + base + j0 + 4);
            xa[0]=v0.x; xa[1]=v0.y; xa[2]=v0.z; xa[3]=v0.w;
            xa[4]=v1.x; xa[5]=v1.y; xa[6]=v1.z; xa[7]=v1.w;
            v0 = *(const float4*)(xb + base + 1024 + j0);
            v1 = *(const float4*)(xb + base + 1024 + j0 + 4);
            xd[0]=v0.x; xd[1]=v0.y; xd[2]=v0.z; xd[3]=v0.w;
            xd[4]=v1.x; xd[5]=v1.y; xd[6]=v1.z; xd[7]=v1.w;
            // reversed stream 2: indices base+2048-j0-7 .. base+2048-j0 (start ≡ 1 mod 4)
            {
                int s = base + 2048 - j0 - 8;   // aligned base (s ≡ 0 mod 4)
                float4 w0 = *(const float4*)(xb + s);
                float4 w1 = *(const float4*)(xb + s + 4);
                float4 w2 = *(const float4*)(xb + s + 8);
                // seg[i] = x[s+1+i], i=0..7 ; xr2[e] = x[base+2048-j0-e] = seg[7-e]
                float seg[8] = {w0.y, w0.z, w0.w, w1.x, w1.y, w1.z, w1.w, w2.x};
                #pragma unroll
                for (int e = 0; e < 8; e++) xr2[e] = seg[7 - e];
            }
            // reversed stream 1: indices base+1024-j0-7 .. base+1024-j0
            {
                int s = base + 1024 - j0 - 8;
                float4 w0 = *(const float4*)(xb + s);
                float4 w1 = *(const float4*)(xb + s + 4);
                float4 w2 = *(const float4*)(xb + s + 8);
                float seg[8] = {w0.y, w0.z, w0.w, w1.x, w1.y, w1.z, w1.w, w2.x};
                #pragma unroll
                for (int e = 0; e < 8; e++) xr1[e] = seg[7 - e];
            }
        } else {
            #pragma unroll
            for (int e = 0; e < 8; e++) {
                int j = j0 + e;
                xa[e]  = xrefl(xb, base + j);
                xd[e]  = xrefl(xb, base + 1024 + j);
                xr2[e] = xrefl(xb, base + 2048 - j);
                xr1[e] = xrefl(xb, base + 1024 - j);
            }
        }

        __half hpe[8], hpo[8], hme[8], hmo[8];
        #pragma unroll
        for (int e = 0; e < 8; e++) {
            int j = j0 + e;
            float vpe = 0.f, vpo = 0.f, vme = 0.f, vmo = 0.f;
            if (j <= 512) {
                float winj = g_win[j];
                float winp = 1.0f - winj;
                float qa = winj * (xa[e] + xr2[e]);
                float qb = winp * (xr1[e] + xd[e]);
                float ma = winj * (xa[e] - xr2[e]);
                float mb = winp * (xr1[e] - xd[e]);
                float h = (j == 0 || j == 512) ? 0.5f : 1.0f;
                vpe = (qa + qb) * h;
                vpo = (qa - qb) * h;
                vme = (ma - mb) * h;
                vmo = (ma + mb) * h;
                alt += (j & 1) ? -vpe : vpe;
            }
            hpe[e] = __float2half_rn(vpe);
            hpo[e] = __float2half_rn(vpo);
            hme[e] = __float2half_rn(vme);
            hmo[e] = __float2half_rn(vmo);
        }
        *(uint4*)(pe + j0) = *(uint4*)hpe;
        *(uint4*)(po + j0) = *(uint4*)hpo;
        *(uint4*)(me + j0) = *(uint4*)hme;
        *(uint4*)(mo + j0) = *(uint4*)hmo;
    }

    if (alt != 0.f) atomicAdd(&alt4[c], alt);
    __syncthreads();
    if (tid < 4) {
        int cc = blockIdx.x * 4 + tid;
        if (cc < NCOLS) {
            int b = cc / FRAMES;
            int t = cc - b * FRAMES;
            const size_t TOT = (size_t)BATCH * NFFT * FRAMES;
            size_t o = ((size_t)b * NFFT + 1024) * FRAMES + t;
            out[o] = alt4[tid];
            out[TOT + o] = 0.f;
        }
    }
}

// ---- main GEMM: CTA 128x128, 2 CTAs/SM, 4 phases (unchanged from R10) ----
__global__ __launch_bounds__(256, 2) void stft_mma5(float* __restrict__ out)
{
    extern __shared__ __align__(128) char smem[];
    const uint32_t sb = smem_u32(smem);
    const int tid  = threadIdx.x;
    const int lane = tid & 31;
    const int wid  = tid >> 5;
    const int ct    = blockIdx.x;
    const int k0    = blockIdx.y * MT2;
    const int phase = blockIdx.z;
    const int wm = wid & 1;
    const int wn = wid >> 1;
    const int par    = phase & 1;
    const int is_sin = phase >> 1;

    uint32_t dstT[4]; uint64_t srcT[4];
    #pragma unroll
    for (int r = 0; r < 4; r++) {
        int idx = tid + r * 256;
        int row = idx >> 3, kg = idx & 7;
        dstT[r] = (uint32_t)(row * 128 + ((kg ^ (row & 7)) << 4));
        srcT[r] = (uint64_t)row * (KP2 * 2) + (uint64_t)kg * 16;
    }
    uint64_t gA, gB;
    { const __half* p = g_W + (size_t)phase * MROWS * KP2 + (size_t)k0 * KP2;
      asm("cvta.to.global.u64 %0, %1;" : "=l"(gA) : "l"(p)); }
    { const __half* p = g_B + (size_t)phase * NPAD * KP2 + (size_t)ct * NT2 * KP2;
      asm("cvta.to.global.u64 %0, %1;" : "=l"(gB) : "l"(p)); }

    float acc[4][4][4];
    #pragma unroll
    for (int a = 0; a < 4; a++)
        #pragma unroll
        for (int b = 0; b < 4; b++)
            #pragma unroll
            for (int c = 0; c < 4; c++) acc[a][b][c] = 0.f;

    #pragma unroll
    for (int i = 0; i < 2; i++) {
        uint32_t st = sb + i * STAGE_BYTES;
        uint64_t off = (uint64_t)i * (KC * 2);
        #pragma unroll
        for (int r = 0; r < 4; r++) {
            cpa(st + dstT[r],           gA + off + srcT[r]);
            cpa(st + A_BYTES + dstT[r], gB + off + srcT[r]);
        }
        asm volatile("cp.async.commit_group;" ::: "memory");
    }

    const int arow = lane & 15;
    const int ahi  = (lane >> 4) & 1;
    const int bcol = wn * 32 + (lane & 7) + (((lane >> 4) & 1) << 3);
    const int bhi  = (lane >> 3) & 1;

    int s = 0;
    for (int i = 0; i < NCH; i++) {
        if (i < NCH - 1)
            asm volatile("cp.async.wait_group 1;" ::: "memory");
        else
            asm volatile("cp.async.wait_group 0;" ::: "memory");
        __syncthreads();

        const uint32_t st = sb + s * STAGE_BYTES;
        const uint32_t aBase = st + wm * (64 * 128);
        const uint32_t bBase = st + A_BYTES;
        #pragma unroll
        for (int ks = 0; ks < 4; ks++) {
            uint32_t bf[2][4];
            #pragma unroll
            for (int nt2 = 0; nt2 < 2; nt2++) {
                int col = bcol + nt2 * 16;
                int kg = ks * 2 + bhi;
                ldsm4(bf[nt2], bBase + col * 128 + ((kg ^ (col & 7)) << 4));
            }
            #pragma unroll
            for (int mt = 0; mt < 4; mt++) {
                int row = mt * 16 + arow;
                int kg = ks * 2 + ahi;
                uint32_t af[4];
                ldsm4(af, aBase + row * 128 + ((kg ^ (row & 7)) << 4));
                #pragma unroll
                for (int nt = 0; nt < 4; nt++)
                    mma16(acc[mt][nt], af, &bf[nt >> 1][(nt & 1) * 2]);
            }
        }

        if (i + 2 < NCH) {
            int s2 = s + 2; if (s2 >= STAGES) s2 -= STAGES;
            uint32_t st2 = sb + s2 * STAGE_BYTES;
            uint64_t off = (uint64_t)(i + 2) * (KC * 2);
            #pragma unroll
            for (int r = 0; r < 4; r++) {
                cpa(st2 + dstT[r],           gA + off + srcT[r]);
                cpa(st2 + A_BYTES + dstT[r], gB + off + srcT[r]);
            }
            asm volatile("cp.async.commit_group;" ::: "memory");
        }
        s++; if (s == STAGES) s = 0;
    }

    const size_t TOT = (size_t)BATCH * NFFT * FRAMES;
    #pragma unroll
    for (int nt = 0; nt < 4; nt++) {
        int gc = ct * NT2 + wn * 32 + nt * 8 + (lane & 3) * 2;
        #pragma unroll
        for (int p = 0; p < 2; p++) {
            int g = gc + p;
            if (g >= NCOLS) continue;
            int b = g / FRAMES;
            int t = g - b * FRAMES;
            size_t cb = (size_t)b * ((size_t)NFFT * FRAMES) + t;
            #pragma unroll
            for (int mt = 0; mt < 4; mt++) {
                int m = k0 + wm * 64 + mt * 16 + (lane >> 2);
                int k = 2 * m + par;
                float v0 = acc[mt][nt][p];
                float v1 = acc[mt][nt][2 + p];
                if (!is_sin) {
                    out[cb + (size_t)k * FRAMES] = v0;
                    out[cb + (size_t)(k + 16) * FRAMES] = v1;
                    if (k >= 1) out[cb + (size_t)(NFFT - k) * FRAMES] = v0;
                    out[cb + (size_t)(NFFT - k - 16) * FRAMES] = v1;
                } else {
                    out[TOT + cb + (size_t)k * FRAMES] = -v0;
                    out[TOT + cb + (size_t)(k + 16) * FRAMES] = -v1;
                    if (k >= 1) out[TOT + cb + (size_t)(NFFT - k) * FRAMES] = v0;
                    out[TOT + cb + (size_t)(NFFT - k - 16) * FRAMES] = v1;
                }
            }
        }
    }
}

extern "C" void kernel_launch(void* const* d_in, const int* in_sizes, int n_in,
                              void* d_out, int out_size) {
    const float* x = (const float*)d_in[0];
    float* out = (float*)d_out;

    cudaFuncSetAttribute(stft_mma5, cudaFuncAttributeMaxDynamicSharedMemorySize, SMEM_TOTAL);

    build_W<<<(MROWS * KP2 + 255) / 256, 256>>>();
    build_B4v<<<NPAD / 4, 288>>>(x, out);
    stft_mma5<<<dim3(NPAD / NT2, MROWS / MT2, 4), 256, SMEM_TOTAL>>>(out);
}

// round 12
// speedup vs baseline: 1.0691x; 1.0691x over previous
#include <cuda_runtime.h>
#include <cuda_fp16.h>
#include <cstdint>

#define LENGTH   262144
#define NFFT     2048
#define HOP      512
#define BATCH    16
#define FRAMES   513
#define NCOLS    (BATCH * FRAMES)      // 8208
#define NPAD     8448                  // 66 * 128
#define KP2      576                   // 513 live + pad (9 chunks of 64)
#define KC       64
#define NCH      (KP2 / KC)            // 9
#define MROWS    512
#define MT2      128
#define NT2      128
#define A_BYTES  (MT2 * 128)
#define B_BYTES  (NT2 * 128)
#define STAGE_BYTES (A_BYTES + B_BYTES) // 32768
#define STAGES   3
#define SMEM_TOTAL (STAGES * STAGE_BYTES) // 98304
#define WBLOCKS  ((MROWS * KP2 + 255) / 256)   // 1152

// phase order: 0=even-cos(Pe), 1=odd-cos(Po), 2=even-sin(Me), 3=odd-sin(Mo)
__device__ __align__(16) __half g_W[4 * MROWS * KP2];   // 2.4 MB
__device__ __align__(16) __half g_B[4 * NPAD * KP2];    // 38.9 MB

__device__ __forceinline__ uint32_t smem_u32(const void* p) {
    uint32_t a;
    asm("{ .reg .u64 t; cvta.to.shared.u64 t, %1; cvt.u32.u64 %0, t; }" : "=r"(a) : "l"(p));
    return a;
}
__device__ __forceinline__ void cpa(uint32_t dst, uint64_t gsrc) {
    asm volatile("cp.async.cg.shared.global [%0], [%1], 16;" :: "r"(dst), "l"(gsrc) : "memory");
}
__device__ __forceinline__ void ldsm4(uint32_t* r, uint32_t a) {
    asm volatile("ldmatrix.sync.aligned.m8n8.x4.shared.b16 {%0,%1,%2,%3}, [%4];"
        : "=r"(r[0]), "=r"(r[1]), "=r"(r[2]), "=r"(r[3]) : "r"(a));
}
__device__ __forceinline__ void mma16(float* c, const uint32_t* a, const uint32_t* b) {
    asm volatile("mma.sync.aligned.m16n8k16.row.col.f32.f16.f16.f32 "
        "{%0,%1,%2,%3}, {%4,%5,%6,%7}, {%8,%9}, {%0,%1,%2,%3};"
        : "+f"(c[0]), "+f"(c[1]), "+f"(c[2]), "+f"(c[3])
        : "r"(a[0]), "r"(a[1]), "r"(a[2]), "r"(a[3]), "r"(b[0]), "r"(b[1]));
}
__device__ __forceinline__ float xrefl(const float* xb, int i) {
    if (i < 0) i = -i;
    else if (i >= LENGTH) i = 2 * LENGTH - 2 - i;
    return xb[i];
}

// ---- fused prep: blocks [0, NPAD) build B (one column each, smem-staged);
//      blocks [NPAD, NPAD+WBLOCKS) build W ----
__global__ __launch_bounds__(256) void prep_all(const float* __restrict__ x,
                                                float* __restrict__ out)
{
    const int tid = threadIdx.x;

    if (blockIdx.x >= NPAD) {
        // ---------- W builder ----------
        int idx = (blockIdx.x - NPAD) * 256 + tid;
        if (idx >= MROWS * KP2) return;
        int m = idx / KP2;
        int n = idx - m * KP2;
        float ce = 0.f, co = 0.f, se = 0.f, so = 0.f;
        if (n <= 512) {
            float ue = (float)(m * n) / 512.0f;
            float uo = (float)((2 * m + 1) * n) / 1024.0f;
            ce = cospif(ue); se = sinpif(ue);
            co = cospif(uo); so = sinpif(uo);
        }
        g_W[0 * MROWS * KP2 + idx] = __float2half_rn(ce);
        g_W[1 * MROWS * KP2 + idx] = __float2half_rn(co);
        g_W[2 * MROWS * KP2 + idx] = __float2half_rn(se);
        g_W[3 * MROWS * KP2 + idx] = __float2half_rn(so);
        return;
    }

    // ---------- B builder: one column per block ----------
    __shared__ __align__(16) float xs[2052];
    __shared__ float red[8];
    const int col = blockIdx.x;

    __half* pe = g_B + 0 * (size_t)NPAD * KP2 + (size_t)col * KP2;
    __half* po = g_B + 1 * (size_t)NPAD * KP2 + (size_t)col * KP2;
    __half* me = g_B + 2 * (size_t)NPAD * KP2 + (size_t)col * KP2;
    __half* mo = g_B + 3 * (size_t)NPAD * KP2 + (size_t)col * KP2;

    if (col >= NCOLS) {                 // pad columns: zero fill
        __half2 z = __floats2half2_rn(0.f, 0.f);
        for (int jp = tid; jp < 288; jp += 256) {
            int j = jp * 2;
            *(__half2*)(pe + j) = z; *(__half2*)(po + j) = z;
            *(__half2*)(me + j) = z; *(__half2*)(mo + j) = z;
        }
        return;
    }

    const int b = col / FRAMES;
    const int t = col - b * FRAMES;
    const float* __restrict__ xb = x + (size_t)b * LENGTH;
    const int base = t * HOP - 1024;

    // stage x[base .. base+2048] -> xs[0..2048], coalesced float4
    for (int u = tid; u < 513; u += 256) {
        int gi = base + u * 4;
        float4 v;
        if (gi >= 0 && gi + 3 < LENGTH) {
            v = *(const float4*)(xb + gi);
        } else {
            float* vv = (float*)&v;
            #pragma unroll
            for (int e = 0; e < 4; e++) vv[e] = xrefl(xb, gi + e);
        }
        *(float4*)&xs[u * 4] = v;
    }
    __syncthreads();

    float alt = 0.f;                    // Σ (−1)^j vpe  -> real[k=1024]
    for (int jp = tid; jp < 288; jp += 256) {
        int j = jp * 2;
        float r_pe[2], r_po[2], r_me[2], r_mo[2];
        #pragma unroll
        for (int e = 0; e < 2; e++) {
            int jj = j + e;
            float vpe = 0.f, vpo = 0.f, vme = 0.f, vmo = 0.f;
            if (jj <= 512) {
                float winj = 0.5f - 0.5f * cospif((float)jj / 1024.0f);
                float winp = 1.0f - winj;
                float xa  = xs[jj];
                float xd  = xs[1024 + jj];
                float xr2 = xs[2048 - jj];
                float xr1 = xs[1024 - jj];
                float qa = winj * (xa + xr2);
                float qb = winp * (xr1 + xd);
                float ma = winj * (xa - xr2);
                float mb = winp * (xr1 - xd);
                float h = (jj == 0 || jj == 512) ? 0.5f : 1.0f;
                vpe = (qa + qb) * h;
                vpo = (qa - qb) * h;
                vme = (ma - mb) * h;
                vmo = (ma + mb) * h;
                alt += (jj & 1) ? -vpe : vpe;
            }
            r_pe[e] = vpe; r_po[e] = vpo; r_me[e] = vme; r_mo[e] = vmo;
        }
        *(__half2*)(pe + j) = __floats2half2_rn(r_pe[0], r_pe[1]);
        *(__half2*)(po + j) = __floats2half2_rn(r_po[0], r_po[1]);
        *(__half2*)(me + j) = __floats2half2_rn(r_me[0], r_me[1]);
        *(__half2*)(mo + j) = __floats2half2_rn(r_mo[0], r_mo[1]);
    }

    // block-reduce alt -> out[k=1024]
    #pragma unroll
    for (int off = 16; off > 0; off >>= 1)
        alt += __shfl_down_sync(0xFFFFFFFF, alt, off);
    if ((tid & 31) == 0) red[tid >> 5] = alt;
    __syncthreads();
    if (tid == 0) {
        float s = 0.f;
        #pragma unroll
        for (int w = 0; w < 8; w++) s += red[w];
        const size_t TOT = (size_t)BATCH * NFFT * FRAMES;
        size_t o = ((size_t)b * NFFT + 1024) * FRAMES + t;
        out[o] = s;
        out[TOT + o] = 0.f;
    }
}

// ---- main GEMM: CTA 128x128, 2 CTAs/SM, 4 phases (identical to R10) ----
__global__ __launch_bounds__(256, 2) void stft_mma5(float* __restrict__ out)
{
    extern __shared__ __align__(128) char smem[];
    const uint32_t sb = smem_u32(smem);
    const int tid  = threadIdx.x;
    const int lane = tid & 31;
    const int wid  = tid >> 5;
    const int ct    = blockIdx.x;
    const int k0    = blockIdx.y * MT2;
    const int phase = blockIdx.z;
    const int wm = wid & 1;
    const int wn = wid >> 1;
    const int par    = phase & 1;
    const int is_sin = phase >> 1;

    uint32_t dstT[4]; uint64_t srcT[4];
    #pragma unroll
    for (int r = 0; r < 4; r++) {
        int idx = tid + r * 256;
        int row = idx >> 3, kg = idx & 7;
        dstT[r] = (uint32_t)(row * 128 + ((kg ^ (row & 7)) << 4));
        srcT[r] = (uint64_t)row * (KP2 * 2) + (uint64_t)kg * 16;
    }
    uint64_t gA, gB;
    { const __half* p = g_W + (size_t)phase * MROWS * KP2 + (size_t)k0 * KP2;
      asm("cvta.to.global.u64 %0, %1;" : "=l"(gA) : "l"(p)); }
    { const __half* p = g_B + (size_t)phase * NPAD * KP2 + (size_t)ct * NT2 * KP2;
      asm("cvta.to.global.u64 %0, %1;" : "=l"(gB) : "l"(p)); }

    float acc[4][4][4];
    #pragma unroll
    for (int a = 0; a < 4; a++)
        #pragma unroll
        for (int b = 0; b < 4; b++)
            #pragma unroll
            for (int c = 0; c < 4; c++) acc[a][b][c] = 0.f;

    #pragma unroll
    for (int i = 0; i < 2; i++) {
        uint32_t st = sb + i * STAGE_BYTES;
        uint64_t off = (uint64_t)i * (KC * 2);
        #pragma unroll
        for (int r = 0; r < 4; r++) {
            cpa(st + dstT[r],           gA + off + srcT[r]);
            cpa(st + A_BYTES + dstT[r], gB + off + srcT[r]);
        }
        asm volatile("cp.async.commit_group;" ::: "memory");
    }

    const int arow = lane & 15;
    const int ahi  = (lane >> 4) & 1;
    const int bcol = wn * 32 + (lane & 7) + (((lane >> 4) & 1) << 3);
    const int bhi  = (lane >> 3) & 1;

    int s = 0;
    for (int i = 0; i < NCH; i++) {
        if (i < NCH - 1)
            asm volatile("cp.async.wait_group 1;" ::: "memory");
        else
            asm volatile("cp.async.wait_group 0;" ::: "memory");
        __syncthreads();

        const uint32_t st = sb + s * STAGE_BYTES;
        const uint32_t aBase = st + wm * (64 * 128);
        const uint32_t bBase = st + A_BYTES;
        #pragma unroll
        for (int ks = 0; ks < 4; ks++) {
            uint32_t bf[2][4];
            #pragma unroll
            for (int nt2 = 0; nt2 < 2; nt2++) {
                int col = bcol + nt2 * 16;
                int kg = ks * 2 + bhi;
                ldsm4(bf[nt2], bBase + col * 128 + ((kg ^ (col & 7)) << 4));
            }
            #pragma unroll
            for (int mt = 0; mt < 4; mt++) {
                int row = mt * 16 + arow;
                int kg = ks * 2 + ahi;
                uint32_t af[4];
                ldsm4(af, aBase + row * 128 + ((kg ^ (row & 7)) << 4));
                #pragma unroll
                for (int nt = 0; nt < 4; nt++)
                    mma16(acc[mt][nt], af, &bf[nt >> 1][(nt & 1) * 2]);
            }
        }

        if (i + 2 < NCH) {
            int s2 = s + 2; if (s2 >= STAGES) s2 -= STAGES;
            uint32_t st2 = sb + s2 * STAGE_BYTES;
            uint64_t off = (uint64_t)(i + 2) * (KC * 2);
            #pragma unroll
            for (int r = 0; r < 4; r++) {
                cpa(st2 + dstT[r],           gA + off + srcT[r]);
                cpa(st2 + A_BYTES + dstT[r], gB + off + srcT[r]);
            }
            asm volatile("cp.async.commit_group;" ::: "memory");
        }
        s++; if (s == STAGES) s = 0;
    }

    const size_t TOT = (size_t)BATCH * NFFT * FRAMES;
    #pragma unroll
    for (int nt = 0; nt < 4; nt++) {
        int gc = ct * NT2 + wn * 32 + nt * 8 + (lane & 3) * 2;
        #pragma unroll
        for (int p = 0; p < 2; p++) {
            int g = gc + p;
            if (g >= NCOLS) continue;
            int b = g / FRAMES;
            int t = g - b * FRAMES;
            size_t cb = (size_t)b * ((size_t)NFFT * FRAMES) + t;
            #pragma unroll
            for (int mt = 0; mt < 4; mt++) {
                int m = k0 + wm * 64 + mt * 16 + (lane >> 2);
                int k = 2 * m + par;
                float v0 = acc[mt][nt][p];
                float v1 = acc[mt][nt][2 + p];
                if (!is_sin) {
                    out[cb + (size_t)k * FRAMES] = v0;
                    out[cb + (size_t)(k + 16) * FRAMES] = v1;
                    if (k >= 1) out[cb + (size_t)(NFFT - k) * FRAMES] = v0;
                    out[cb + (size_t)(NFFT - k - 16) * FRAMES] = v1;
                } else {
                    out[TOT + cb + (size_t)k * FRAMES] = -v0;
                    out[TOT + cb + (size_t)(k + 16) * FRAMES] = -v1;
                    if (k >= 1) out[TOT + cb + (size_t)(NFFT - k) * FRAMES] = v0;
                    out[TOT + cb + (size_t)(NFFT - k - 16) * FRAMES] = v1;
                }
            }
        }
    }
}

extern "C" void kernel_launch(void* const* d_in, const int* in_sizes, int n_in,
                              void* d_out, int out_size) {
    const float* x = (const float*)d_in[0];
    float* out = (float*)d_out;

    cudaFuncSetAttribute(stft_mma5, cudaFuncAttributeMaxDynamicSharedMemorySize, SMEM_TOTAL);

    prep_all<<<NPAD + WBLOCKS, 256>>>(x, out);
    stft_mma5<<<dim3(NPAD / NT2, MROWS / MT2, 4), 256, SMEM_TOTAL>>>(out);
}

// round 13
// speedup vs baseline: 2.3117x; 2.1623x over previous
#include <cuda_runtime.h>
#include <cuda_fp16.h>
#include <cstdint>

#define LENGTH   262144
#define NFFT     2048
#define HOP      512
#define BATCH    16
#define FRAMES   513
#define NCOLS    (BATCH * FRAMES)      // 8208
#define NPAD     8448                  // 66 * 128
#define KP2      576                   // 513 live + pad (9 chunks of 64)
#define KC       64
#define NCH      (KP2 / KC)            // 9
#define MROWS    512
#define MT2      128
#define NT2      128
#define A_BYTES  (MT2 * 128)
#define B_BYTES  (NT2 * 128)
#define STAGE_BYTES (A_BYTES + B_BYTES) // 32768
#define STAGES   3
#define SMEM_TOTAL (STAGES * STAGE_BYTES) // 98304 (>= 128*132*4 = 67584 for epilogue)
#define WBLOCKS  ((MROWS * KP2 + 255) / 256)   // 1152

// phase order: 0=even-cos(Pe), 1=odd-cos(Po), 2=even-sin(Me), 3=odd-sin(Mo)
__device__ __align__(16) __half g_W[4 * MROWS * KP2];   // 2.4 MB
__device__ __align__(16) __half g_B[4 * NPAD * KP2];    // 38.9 MB

__device__ __forceinline__ uint32_t smem_u32(const void* p) {
    uint32_t a;
    asm("{ .reg .u64 t; cvta.to.shared.u64 t, %1; cvt.u32.u64 %0, t; }" : "=r"(a) : "l"(p));
    return a;
}
__device__ __forceinline__ void cpa(uint32_t dst, uint64_t gsrc) {
    asm volatile("cp.async.cg.shared.global [%0], [%1], 16;" :: "r"(dst), "l"(gsrc) : "memory");
}
__device__ __forceinline__ void ldsm4(uint32_t* r, uint32_t a) {
    asm volatile("ldmatrix.sync.aligned.m8n8.x4.shared.b16 {%0,%1,%2,%3}, [%4];"
        : "=r"(r[0]), "=r"(r[1]), "=r"(r[2]), "=r"(r[3]) : "r"(a));
}
__device__ __forceinline__ void mma16(float* c, const uint32_t* a, const uint32_t* b) {
    asm volatile("mma.sync.aligned.m16n8k16.row.col.f32.f16.f16.f32 "
        "{%0,%1,%2,%3}, {%4,%5,%6,%7}, {%8,%9}, {%0,%1,%2,%3};"
        : "+f"(c[0]), "+f"(c[1]), "+f"(c[2]), "+f"(c[3])
        : "r"(a[0]), "r"(a[1]), "r"(a[2]), "r"(a[3]), "r"(b[0]), "r"(b[1]));
}
__device__ __forceinline__ float xrefl(const float* xb, int i) {
    if (i < 0) i = -i;
    else if (i >= LENGTH) i = 2 * LENGTH - 2 - i;
    return xb[i];
}

// ---- fused prep (identical to R12) ----
__global__ __launch_bounds__(256) void prep_all(const float* __restrict__ x,
                                                float* __restrict__ out)
{
    const int tid = threadIdx.x;

    if (blockIdx.x >= NPAD) {
        int idx = (blockIdx.x - NPAD) * 256 + tid;
        if (idx >= MROWS * KP2) return;
        int m = idx / KP2;
        int n = idx - m * KP2;
        float ce = 0.f, co = 0.f, se = 0.f, so = 0.f;
        if (n <= 512) {
            float ue = (float)(m * n) / 512.0f;
            float uo = (float)((2 * m + 1) * n) / 1024.0f;
            ce = cospif(ue); se = sinpif(ue);
            co = cospif(uo); so = sinpif(uo);
        }
        g_W[0 * MROWS * KP2 + idx] = __float2half_rn(ce);
        g_W[1 * MROWS * KP2 + idx] = __float2half_rn(co);
        g_W[2 * MROWS * KP2 + idx] = __float2half_rn(se);
        g_W[3 * MROWS * KP2 + idx] = __float2half_rn(so);
        return;
    }

    __shared__ __align__(16) float xs[2052];
    __shared__ float red[8];
    const int col = blockIdx.x;

    __half* pe = g_B + 0 * (size_t)NPAD * KP2 + (size_t)col * KP2;
    __half* po = g_B + 1 * (size_t)NPAD * KP2 + (size_t)col * KP2;
    __half* me = g_B + 2 * (size_t)NPAD * KP2 + (size_t)col * KP2;
    __half* mo = g_B + 3 * (size_t)NPAD * KP2 + (size_t)col * KP2;

    if (col >= NCOLS) {
        __half2 z = __floats2half2_rn(0.f, 0.f);
        for (int jp = tid; jp < 288; jp += 256) {
            int j = jp * 2;
            *(__half2*)(pe + j) = z; *(__half2*)(po + j) = z;
            *(__half2*)(me + j) = z; *(__half2*)(mo + j) = z;
        }
        return;
    }

    const int b = col / FRAMES;
    const int t = col - b * FRAMES;
    const float* __restrict__ xb = x + (size_t)b * LENGTH;
    const int base = t * HOP - 1024;

    for (int u = tid; u < 513; u += 256) {
        int gi = base + u * 4;
        float4 v;
        if (gi >= 0 && gi + 3 < LENGTH) {
            v = *(const float4*)(xb + gi);
        } else {
            float* vv = (float*)&v;
            #pragma unroll
            for (int e = 0; e < 4; e++) vv[e] = xrefl(xb, gi + e);
        }
        *(float4*)&xs[u * 4] = v;
    }
    __syncthreads();

    float alt = 0.f;
    for (int jp = tid; jp < 288; jp += 256) {
        int j = jp * 2;
        float r_pe[2], r_po[2], r_me[2], r_mo[2];
        #pragma unroll
        for (int e = 0; e < 2; e++) {
            int jj = j + e;
            float vpe = 0.f, vpo = 0.f, vme = 0.f, vmo = 0.f;
            if (jj <= 512) {
                float winj = 0.5f - 0.5f * cospif((float)jj / 1024.0f);
                float winp = 1.0f - winj;
                float xa  = xs[jj];
                float xd  = xs[1024 + jj];
                float xr2 = xs[2048 - jj];
                float xr1 = xs[1024 - jj];
                float qa = winj * (xa + xr2);
                float qb = winp * (xr1 + xd);
                float ma = winj * (xa - xr2);
                float mb = winp * (xr1 - xd);
                float h = (jj == 0 || jj == 512) ? 0.5f : 1.0f;
                vpe = (qa + qb) * h;
                vpo = (qa - qb) * h;
                vme = (ma - mb) * h;
                vmo = (ma + mb) * h;
                alt += (jj & 1) ? -vpe : vpe;
            }
            r_pe[e] = vpe; r_po[e] = vpo; r_me[e] = vme; r_mo[e] = vmo;
        }
        *(__half2*)(pe + j) = __floats2half2_rn(r_pe[0], r_pe[1]);
        *(__half2*)(po + j) = __floats2half2_rn(r_po[0], r_po[1]);
        *(__half2*)(me + j) = __floats2half2_rn(r_me[0], r_me[1]);
        *(__half2*)(mo + j) = __floats2half2_rn(r_mo[0], r_mo[1]);
    }

    #pragma unroll
    for (int off = 16; off > 0; off >>= 1)
        alt += __shfl_down_sync(0xFFFFFFFF, alt, off);
    if ((tid & 31) == 0) red[tid >> 5] = alt;
    __syncthreads();
    if (tid == 0) {
        float s = 0.f;
        #pragma unroll
        for (int w = 0; w < 8; w++) s += red[w];
        const size_t TOT = (size_t)BATCH * NFFT * FRAMES;
        size_t o = ((size_t)b * NFFT + 1024) * FRAMES + t;
        out[o] = s;
        out[TOT + o] = 0.f;
    }
}

// ---- main GEMM: CTA 128x128, 2 CTAs/SM, coalesced smem-staged epilogue ----
__global__ __launch_bounds__(256, 2) void stft_mma6(float* __restrict__ out)
{
    extern __shared__ __align__(128) char smem[];
    const uint32_t sb = smem_u32(smem);
    const int tid  = threadIdx.x;
    const int lane = tid & 31;
    const int wid  = tid >> 5;
    const int ct    = blockIdx.x;
    const int k0    = blockIdx.y * MT2;
    const int phase = blockIdx.z;
    const int wm = wid & 1;
    const int wn = wid >> 1;
    const int par    = phase & 1;
    const int is_sin = phase >> 1;

    uint32_t dstT[4]; uint64_t srcT[4];
    #pragma unroll
    for (int r = 0; r < 4; r++) {
        int idx = tid + r * 256;
        int row = idx >> 3, kg = idx & 7;
        dstT[r] = (uint32_t)(row * 128 + ((kg ^ (row & 7)) << 4));
        srcT[r] = (uint64_t)row * (KP2 * 2) + (uint64_t)kg * 16;
    }
    uint64_t gA, gB;
    { const __half* p = g_W + (size_t)phase * MROWS * KP2 + (size_t)k0 * KP2;
      asm("cvta.to.global.u64 %0, %1;" : "=l"(gA) : "l"(p)); }
    { const __half* p = g_B + (size_t)phase * NPAD * KP2 + (size_t)ct * NT2 * KP2;
      asm("cvta.to.global.u64 %0, %1;" : "=l"(gB) : "l"(p)); }

    float acc[4][4][4];
    #pragma unroll
    for (int a = 0; a < 4; a++)
        #pragma unroll
        for (int b = 0; b < 4; b++)
            #pragma unroll
            for (int c = 0; c < 4; c++) acc[a][b][c] = 0.f;

    #pragma unroll
    for (int i = 0; i < 2; i++) {
        uint32_t st = sb + i * STAGE_BYTES;
        uint64_t off = (uint64_t)i * (KC * 2);
        #pragma unroll
        for (int r = 0; r < 4; r++) {
            cpa(st + dstT[r],           gA + off + srcT[r]);
            cpa(st + A_BYTES + dstT[r], gB + off + srcT[r]);
        }
        asm volatile("cp.async.commit_group;" ::: "memory");
    }

    const int arow = lane & 15;
    const int ahi  = (lane >> 4) & 1;
    const int bcol = wn * 32 + (lane & 7) + (((lane >> 4) & 1) << 3);
    const int bhi  = (lane >> 3) & 1;

    int s = 0;
    for (int i = 0; i < NCH; i++) {
        if (i < NCH - 1)
            asm volatile("cp.async.wait_group 1;" ::: "memory");
        else
            asm volatile("cp.async.wait_group 0;" ::: "memory");
        __syncthreads();

        const uint32_t st = sb + s * STAGE_BYTES;
        const uint32_t aBase = st + wm * (64 * 128);
        const uint32_t bBase = st + A_BYTES;
        #pragma unroll
        for (int ks = 0; ks < 4; ks++) {
            uint32_t bf[2][4];
            #pragma unroll
            for (int nt2 = 0; nt2 < 2; nt2++) {
                int col = bcol + nt2 * 16;
                int kg = ks * 2 + bhi;
                ldsm4(bf[nt2], bBase + col * 128 + ((kg ^ (col & 7)) << 4));
            }
            #pragma unroll
            for (int mt = 0; mt < 4; mt++) {
                int row = mt * 16 + arow;
                int kg = ks * 2 + ahi;
                uint32_t af[4];
                ldsm4(af, aBase + row * 128 + ((kg ^ (row & 7)) << 4));
                #pragma unroll
                for (int nt = 0; nt < 4; nt++)
                    mma16(acc[mt][nt], af, &bf[nt >> 1][(nt & 1) * 2]);
            }
        }

        if (i + 2 < NCH) {
            int s2 = s + 2; if (s2 >= STAGES) s2 -= STAGES;
            uint32_t st2 = sb + s2 * STAGE_BYTES;
            uint64_t off = (uint64_t)(i + 2) * (KC * 2);
            #pragma unroll
            for (int r = 0; r < 4; r++) {
                cpa(st2 + dstT[r],           gA + off + srcT[r]);
                cpa(st2 + A_BYTES + dstT[r], gB + off + srcT[r]);
            }
            asm volatile("cp.async.commit_group;" ::: "memory");
        }
        s++; if (s == STAGES) s = 0;
    }

    // ---- epilogue: stage 128x128 tile to smem, then coalesced row stores ----
    __syncthreads();                      // mainloop smem reads complete
    float* stile = (float*)smem;          // 128 x 132 floats = 67584 B
    #pragma unroll
    for (int mt = 0; mt < 4; mt++) {
        #pragma unroll
        for (int nt = 0; nt < 4; nt++) {
            #pragma unroll
            for (int p = 0; p < 2; p++) {
                int row = wm * 64 + mt * 16 + (lane >> 2);
                int c   = wn * 32 + nt * 8 + (lane & 3) * 2 + p;
                stile[row * 132 + c]       = acc[mt][nt][p];
                stile[(row + 8) * 132 + c] = acc[mt][nt][2 + p];
            }
        }
    }
    __syncthreads();

    const size_t TOT = (size_t)BATCH * NFFT * FRAMES;
    const int c = tid & 127;
    const int g = ct * NT2 + c;
    if (g < NCOLS) {
        const int b = g / FRAMES;
        const int t = g - b * FRAMES;
        const size_t cb = (size_t)b * ((size_t)NFFT * FRAMES) + t;
        #pragma unroll 8
        for (int r0 = 0; r0 < 128; r0 += 2) {
            int row = r0 + (tid >> 7);
            int k = 2 * (k0 + row) + par;
            float v = stile[row * 132 + c];
            if (!is_sin) {
                out[cb + (size_t)k * FRAMES] = v;
                if (k >= 1) out[cb + (size_t)(NFFT - k) * FRAMES] = v;
            } else {
                out[TOT + cb + (size_t)k * FRAMES] = -v;
                if (k >= 1) out[TOT + cb + (size_t)(NFFT - k) * FRAMES] = v;
            }
        }
    }
}

extern "C" void kernel_launch(void* const* d_in, const int* in_sizes, int n_in,
                              void* d_out, int out_size) {
    const float* x = (const float*)d_in[0];
    float* out = (float*)d_out;

    cudaFuncSetAttribute(stft_mma6, cudaFuncAttributeMaxDynamicSharedMemorySize, SMEM_TOTAL);

    prep_all<<<NPAD + WBLOCKS, 256>>>(x, out);
    stft_mma6<<<dim3(NPAD / NT2, MROWS / MT2, 4), 256, SMEM_TOTAL>>>(out);
}